// round 4
// baseline (speedup 1.0000x reference)
#include <cuda_runtime.h>
#include <cuda_bf16.h>

#define Nn 100000
#define Ee 1600000
#define Hh 128
#define Gg 64
#define EPSf 1e-5f

#define PITCH 132
#define SCAN_BS 1024
#define NBLK ((Nn + SCAN_BS - 1) / SCAN_BS)   // 98
#define SMEM_GEMM ((128 * PITCH + 128 * 128) * 4)
#define BN_REP 4

#define FFMA2(d, a, b) asm("fma.rn.f32x2 %0, %1, %2, %0;" : "+l"(d) : "l"(a), "l"(b))

// ---------------- device scratch (no allocations allowed) ----------------
__device__ int   g_deg[Nn];
__device__ float g_dinv[Nn];
__device__ int   g_off[Nn + 1];
__device__ int   g_cursor[Nn];
__device__ int   g_bsum[SCAN_BS];
__device__ int2  g_csr[Ee];               // {src, weight-as-int}
__device__ float g_h[(size_t)Nn * Hh];
__device__ float g_agg[(size_t)Nn * Hh];
__device__ float g_act[(size_t)Nn * Hh];
__device__ float g_bnsum[3][BN_REP][2 * Hh];
__device__ float g_bnsc[3][2 * Hh];
__device__ float g_xsum[Gg * Hh];
__device__ float g_cnt[Gg];

// ---------------- zero / degree / dinv ----------------
__global__ void k_zero_pre() {
    int i = blockIdx.x * blockDim.x + threadIdx.x;
    if (i < Nn) { g_deg[i] = 0; g_cursor[i] = 0; }
    if (i < Gg * Hh) g_xsum[i] = 0.0f;
    if (i < Gg) g_cnt[i] = 0.0f;
    if (i < 3 * BN_REP * 2 * Hh) ((float*)g_bnsum)[i] = 0.0f;
}

__global__ void k_deg(const int* __restrict__ dst) {
    int e = blockIdx.x * blockDim.x + threadIdx.x;
    if (e < Ee) atomicAdd(&g_deg[dst[e]], 1);
}

__global__ void k_dinv() {
    int i = blockIdx.x * blockDim.x + threadIdx.x;
    if (i < Nn) g_dinv[i] = rsqrtf((float)g_deg[i] + 1.0f);
}

// ---------------- exclusive scan of degrees -> CSR offsets ----------------
__global__ void k_scan1() {
    __shared__ int s[SCAN_BS];
    int tid = threadIdx.x;
    int i = blockIdx.x * SCAN_BS + tid;
    int v = (i < Nn) ? g_deg[i] : 0;
    s[tid] = v;
    __syncthreads();
    for (int d = 1; d < SCAN_BS; d <<= 1) {
        int t = (tid >= d) ? s[tid - d] : 0;
        __syncthreads();
        s[tid] += t;
        __syncthreads();
    }
    if (i < Nn) g_off[i] = s[tid] - v;
    if (tid == SCAN_BS - 1) g_bsum[blockIdx.x] = s[tid];
}

__global__ void k_scan2() {
    __shared__ int s[128];
    int tid = threadIdx.x;
    int v = (tid < NBLK) ? g_bsum[tid] : 0;
    s[tid] = v;
    __syncthreads();
    for (int d = 1; d < 128; d <<= 1) {
        int t = (tid >= d) ? s[tid - d] : 0;
        __syncthreads();
        s[tid] += t;
        __syncthreads();
    }
    g_bsum[tid] = s[tid] - v;
}

__global__ void k_scan3() {
    int i = blockIdx.x * blockDim.x + threadIdx.x;
    if (i < Nn) g_off[i] += g_bsum[i >> 10];
    if (i == 0) g_off[Nn] = Ee;
}

__global__ void k_fill(const int* __restrict__ src, const int* __restrict__ dst) {
    int e = blockIdx.x * blockDim.x + threadIdx.x;
    if (e >= Ee) return;
    int d = dst[e];
    int s = src[e];
    int pos = g_off[d] + atomicAdd(&g_cursor[d], 1);
    g_csr[pos] = make_int2(s, __float_as_int(g_dinv[s] * g_dinv[d]));
}

// ---- GEMM: g_h[M,128] = A[M,128] @ W[128,128]  (FFMA2), fused BN apply on load ----
// mode 0: A = Ain (plain)
// mode 1: A = relu(bn(g_agg)), also stored to g_act
// mode 2: A = relu(bn(g_agg)) + g_act_old, also stored to g_act
__global__ __launch_bounds__(256) void gemm_k(const float* __restrict__ Ain,
                                              const float* __restrict__ W, int M,
                                              int mode, int bnidx) {
    extern __shared__ float sm[];
    float* Xs = sm;                        // [128][PITCH]
    float* Ws = sm + 128 * PITCH;          // [128][128]

    int tid = threadIdx.x;
    int row0 = blockIdx.x * 128;

    const float4* W4 = (const float4*)W;
    float4* Ws4 = (float4*)Ws;
#pragma unroll
    for (int i = 0; i < 16; i++) Ws4[tid + i * 256] = W4[tid + i * 256];

    int kq = tid & 31;     // channel quad (constant per thread)
    int rb = tid >> 5;     // 0..7

    float4 sc4 = make_float4(0, 0, 0, 0), sh4 = make_float4(0, 0, 0, 0);
    if (mode) {
        sc4 = ((const float4*)g_bnsc[bnidx])[kq];
        sh4 = ((const float4*)g_bnsc[bnidx])[32 + kq];
    }

#pragma unroll
    for (int i = 0; i < 16; i++) {
        int r = rb + i * 8;
        int gr = row0 + r;
        float4 v = make_float4(0.f, 0.f, 0.f, 0.f);
        if (gr < M) {
            if (mode == 0) {
                v = ((const float4*)Ain)[(size_t)gr * 32 + kq];
            } else {
                float4 a = ((const float4*)g_agg)[(size_t)gr * 32 + kq];
                v.x = fmaxf(fmaf(a.x, sc4.x, sh4.x), 0.f);
                v.y = fmaxf(fmaf(a.y, sc4.y, sh4.y), 0.f);
                v.z = fmaxf(fmaf(a.z, sc4.z, sh4.z), 0.f);
                v.w = fmaxf(fmaf(a.w, sc4.w, sh4.w), 0.f);
                if (mode == 2) {
                    float4 rr = ((const float4*)g_act)[(size_t)gr * 32 + kq];
                    v.x += rr.x; v.y += rr.y; v.z += rr.z; v.w += rr.w;
                }
                ((float4*)g_act)[(size_t)gr * 32 + kq] = v;
            }
        }
        ((float4*)(Xs + r * PITCH))[kq] = v;
    }
    __syncthreads();

    int tc = tid & 7;      // 8 col groups x 16 cols
    int tr = tid >> 3;     // 32 row groups x 4 rows

    unsigned long long acc2[4][8];
#pragma unroll
    for (int m = 0; m < 4; m++)
#pragma unroll
        for (int j = 0; j < 8; j++) acc2[m][j] = 0ull;

    const float* xb = Xs + (tr * 4) * PITCH;
    const ulonglong2* Wsr = (const ulonglong2*)Ws;   // 32 ull2 (16B) per 128-float row

#pragma unroll 2
    for (int k = 0; k < 128; k++) {
        unsigned long long xp[4];
#pragma unroll
        for (int m = 0; m < 4; m++) {
            unsigned int xu = __float_as_uint(xb[m * PITCH + k]);
            asm("mov.b64 %0, {%1, %1};" : "=l"(xp[m]) : "r"(xu));
        }
#pragma unroll
        for (int j = 0; j < 4; j++) {
            ulonglong2 w2 = Wsr[k * 32 + tc * 4 + j];
#pragma unroll
            for (int m = 0; m < 4; m++) {
                FFMA2(acc2[m][2 * j],     xp[m], w2.x);
                FFMA2(acc2[m][2 * j + 1], xp[m], w2.y);
            }
        }
    }

    int r0 = row0 + tr * 4;
#pragma unroll
    for (int m = 0; m < 4; m++) {
        if (r0 + m < M) {
            ulonglong2* cp = (ulonglong2*)(g_h + (size_t)(r0 + m) * 128 + tc * 16);
#pragma unroll
            for (int j = 0; j < 4; j++)
                cp[j] = make_ulonglong2(acc2[m][2 * j], acc2[m][2 * j + 1]);
        }
    }
}

// ------- gather + bias + fused BN partial stats (software-pipelined edge loop) -------
// 512 threads = 16 warps = 16 nodes per block; grid covers exactly Nn nodes.
__global__ __launch_bounds__(512) void k_gather(const float* __restrict__ bias, int bnidx) {
    __shared__ float ss[16 * 128];

    int tid = threadIdx.x;
    int wloc = tid >> 5;
    int lane = tid & 31;
    int wid = blockIdx.x * 16 + wloc;   // node id, always < Nn (grid exact)

    int beg = g_off[wid];
    int end = g_off[wid + 1];
    float di = g_dinv[wid];
    float d2 = di * di;

    const float4* hv = (const float4*)g_h;
    float4 hs = hv[(size_t)wid * 32 + lane];
    float4 acc = make_float4(hs.x * d2, hs.y * d2, hs.z * d2, hs.w * d2);

    const int2* csr = g_csr;
    if (beg < end) {
        int2 c = csr[beg];
        float4 v = hv[(size_t)c.x * 32 + lane];
        for (int e = beg + 1; e < end; e++) {
            int2 cn = csr[e];
            float4 vn = hv[(size_t)cn.x * 32 + lane];
            float w = __int_as_float(c.y);
            acc.x = fmaf(v.x, w, acc.x);
            acc.y = fmaf(v.y, w, acc.y);
            acc.z = fmaf(v.z, w, acc.z);
            acc.w = fmaf(v.w, w, acc.w);
            c = cn; v = vn;
        }
        float w = __int_as_float(c.y);
        acc.x = fmaf(v.x, w, acc.x);
        acc.y = fmaf(v.y, w, acc.y);
        acc.z = fmaf(v.z, w, acc.z);
        acc.w = fmaf(v.w, w, acc.w);
    }

    float4 b4 = ((const float4*)bias)[lane];
    acc.x += b4.x; acc.y += b4.y; acc.z += b4.z; acc.w += b4.w;
    ((float4*)g_agg)[(size_t)wid * 32 + lane] = acc;

    int base = wloc * 128 + lane * 4;
    ss[base + 0] = acc.x; ss[base + 1] = acc.y; ss[base + 2] = acc.z; ss[base + 3] = acc.w;
    __syncthreads();

    if (tid < 256) {
        int c = tid & 127;          // channel
        int part = tid >> 7;        // 0 = sum, 1 = sumsq
        float r = 0.f;
        if (part == 0) {
#pragma unroll
            for (int w = 0; w < 16; w++) r += ss[w * 128 + c];
        } else {
#pragma unroll
            for (int w = 0; w < 16; w++) { float v = ss[w * 128 + c]; r = fmaf(v, v, r); }
        }
        atomicAdd(&g_bnsum[bnidx][blockIdx.x & (BN_REP - 1)][part * 128 + c], r);
    }
}

// ---------------- batchnorm finalize (scale/shift coefficients) ----------------
__global__ void k_bnfin(const float* __restrict__ g, const float* __restrict__ be, int bnidx) {
    int c = threadIdx.x;
    float s = 0.f, q = 0.f;
#pragma unroll
    for (int r = 0; r < BN_REP; r++) {
        s += g_bnsum[bnidx][r][c];
        q += g_bnsum[bnidx][r][128 + c];
    }
    float mean = s * (1.0f / (float)Nn);
    float var = q * (1.0f / (float)Nn) - mean * mean;
    float sc = g[c] * rsqrtf(var + EPSf);
    g_bnsc[bnidx][c] = sc;
    g_bnsc[bnidx][128 + c] = be[c] - mean * sc;
}

// ---------------- pooling (batch sorted) with fused layer-3 BN apply ----------------
#define PCHUNK 512
__global__ void k_pool(const int* __restrict__ batch) {
    int c = threadIdx.x;
    int start = blockIdx.x * PCHUNK;
    if (start >= Nn) return;
    int end = min(start + PCHUNK, Nn);
    float sc = g_bnsc[2][c];
    float sh = g_bnsc[2][128 + c];
    float acc = 0.f, ccnt = 0.f;
    int gp = batch[start];
    for (int n = start; n < end; n++) {
        int g = batch[n];
        if (g != gp) {
            atomicAdd(&g_xsum[gp * 128 + c], acc);
            if (c == 0) atomicAdd(&g_cnt[gp], ccnt);
            acc = 0.f; ccnt = 0.f; gp = g;
        }
        float a = g_agg[(size_t)n * 128 + c];
        float v = fmaxf(fmaf(a, sc, sh), 0.f) + g_act[(size_t)n * 128 + c];
        acc += v;
        ccnt += 1.f;
    }
    atomicAdd(&g_xsum[gp * 128 + c], acc);
    if (c == 0) atomicAdd(&g_cnt[gp], ccnt);
}

// ---------------- MLP head ----------------
__global__ void k_mlp(const float* __restrict__ Wm1, const float* __restrict__ bm1,
                      const float* __restrict__ Wm2, const float* __restrict__ bm2,
                      float* __restrict__ out) {
    __shared__ float zs[128], zm[128], hid[128];
    int g = blockIdx.x, c = threadIdx.x;
    float cnt = fmaxf(g_cnt[g], 1.0f);
    float xs = g_xsum[g * 128 + c];
    zs[c] = xs;
    zm[c] = xs / cnt;
    __syncthreads();
    float acc = bm1[c];
#pragma unroll 8
    for (int k = 0; k < 128; k++)
        acc += zs[k] * Wm1[k * 128 + c] + zm[k] * Wm1[(128 + k) * 128 + c];
    hid[c] = fmaxf(acc, 0.f) * Wm2[c];
    __syncthreads();
    for (int s = 64; s > 0; s >>= 1) {
        if (c < s) hid[c] += hid[c + s];
        __syncthreads();
    }
    if (c == 0) out[g] = hid[0] + bm2[0];
}

// ---------------- host ----------------
extern "C" void kernel_launch(void* const* d_in, const int* in_sizes, int n_in,
                              void* d_out, int out_size) {
    const float *x, *W1, *b1, *W2, *b2, *W3, *b3;
    const float *g1, *be1, *g2, *be2, *g3, *be3;
    const float *Wm1, *bm1, *Wm2, *bm2;
    const int *ei, *batch;

    if (in_sizes[1] == 2 * Ee) {
        x   = (const float*)d_in[0];
        ei  = (const int*)  d_in[1];
        batch = (const int*)d_in[2];
        W1 = (const float*)d_in[3];  b1 = (const float*)d_in[4];
        W2 = (const float*)d_in[5];  b2 = (const float*)d_in[6];
        W3 = (const float*)d_in[7];  b3 = (const float*)d_in[8];
        g1 = (const float*)d_in[9];  be1 = (const float*)d_in[10];
        g2 = (const float*)d_in[11]; be2 = (const float*)d_in[12];
        g3 = (const float*)d_in[13]; be3 = (const float*)d_in[14];
        Wm1 = (const float*)d_in[15]; bm1 = (const float*)d_in[16];
        Wm2 = (const float*)d_in[17]; bm2 = (const float*)d_in[18];
    } else {
        x   = (const float*)d_in[0];
        W1 = (const float*)d_in[1];  b1 = (const float*)d_in[2];
        g1 = (const float*)d_in[3];  be1 = (const float*)d_in[4];
        W2 = (const float*)d_in[5];  b2 = (const float*)d_in[6];
        g2 = (const float*)d_in[7];  be2 = (const float*)d_in[8];
        W3 = (const float*)d_in[9];  b3 = (const float*)d_in[10];
        g3 = (const float*)d_in[11]; be3 = (const float*)d_in[12];
        Wm1 = (const float*)d_in[13]; bm1 = (const float*)d_in[14];
        Wm2 = (const float*)d_in[15]; bm2 = (const float*)d_in[16];
        ei  = (const int*)d_in[17];
        batch = (const int*)d_in[18];
    }

    const int* src = ei;
    const int* dst = ei + Ee;
    float* out = (float*)d_out;

    cudaFuncSetAttribute(gemm_k, cudaFuncAttributeMaxDynamicSharedMemorySize, SMEM_GEMM);

    const int ZB = (Nn + 255) / 256;          // 391
    const int EB = (Ee + 255) / 256;          // 6250
    const int GEMMB = (Nn + 127) / 128;       // 782
    const int GATB = (Nn + 15) / 16;          // 6250 blocks x 512 threads
    const int POOLB = (Nn + PCHUNK - 1) / PCHUNK;

    // launches 1-3: preprocessing that does not need CSR
    k_zero_pre<<<ZB, 256>>>();
    k_deg<<<EB, 256>>>(dst);
    k_dinv<<<ZB, 256>>>();

    // launch 4: layer-1 GEMM (independent of edges) — positioned for the ncu capture slot
    gemm_k<<<GEMMB, 256, SMEM_GEMM>>>(x, W1, Nn, 0, 0);

    // finish CSR build
    k_scan1<<<NBLK, SCAN_BS>>>();
    k_scan2<<<1, 128>>>();
    k_scan3<<<ZB, 256>>>();
    k_fill<<<EB, 256>>>(src, dst);

    // layer 1 aggregate + BN stats
    k_gather<<<GATB, 512>>>(b1, 0);
    k_bnfin<<<1, 128>>>(g1, be1, 0);

    // layer 2: GEMM with fused BN1 apply (no residual), then aggregate
    gemm_k<<<GEMMB, 256, SMEM_GEMM>>>(nullptr, W2, Nn, 1, 0);
    k_gather<<<GATB, 512>>>(b2, 1);
    k_bnfin<<<1, 128>>>(g2, be2, 1);

    // layer 3: GEMM with fused BN2 apply + residual, then aggregate
    gemm_k<<<GEMMB, 256, SMEM_GEMM>>>(nullptr, W3, Nn, 2, 1);
    k_gather<<<GATB, 512>>>(b3, 2);
    k_bnfin<<<1, 128>>>(g3, be3, 2);

    // pooling (fused BN3 apply + residual) + MLP
    k_pool<<<POOLB, 128>>>(batch);
    k_mlp<<<Gg, 128>>>(Wm1, bm1, Wm2, bm2, out);
}

// round 6
// speedup vs baseline: 1.6911x; 1.6911x over previous
#include <cuda_runtime.h>
#include <cuda_bf16.h>
#include <cstdint>

#define Nn 100000
#define Ee 1600000
#define Hh 128
#define Gg 64
#define EPSf 1e-5f

#define SCAN_BS 1024
#define NBLK ((Nn + SCAN_BS - 1) / SCAN_BS)   // 98
#define BN_REP 4

// ---------------- mma GEMM smem layout ----------------
#define Pp 136                       // bf16 elements per row (padded; 272 B)
#define IMG (128 * Pp)               // elements per image
#define IMG_B (IMG * 2)              // 34816 bytes per image
#define SM_AHI 0
#define SM_ALO (1 * IMG_B)
#define SM_WHI (2 * IMG_B)
#define SM_WLO (3 * IMG_B)
#define SM_TOTAL (4 * IMG_B)         // 139264 B

#define MMA_BF16(d, a, b0, b1) \
    asm volatile("mma.sync.aligned.m16n8k16.row.col.f32.bf16.bf16.f32 " \
        "{%0,%1,%2,%3}, {%4,%5,%6,%7}, {%8,%9}, {%0,%1,%2,%3};" \
        : "+f"((d)[0]), "+f"((d)[1]), "+f"((d)[2]), "+f"((d)[3]) \
        : "r"((a)[0]), "r"((a)[1]), "r"((a)[2]), "r"((a)[3]), "r"(b0), "r"(b1))

// ---------------- device scratch ----------------
__device__ int   g_deg[Nn];
__device__ float g_dinv[Nn];
__device__ int   g_off[Nn + 1];
__device__ int   g_cursor[Nn];
__device__ int   g_bsum[SCAN_BS];
__device__ int2  g_csr[Ee];
__device__ float g_h[(size_t)Nn * Hh];
__device__ float g_agg[(size_t)Nn * Hh];
__device__ float g_act[(size_t)Nn * Hh];
__device__ float g_bnsum[3][BN_REP][2 * Hh];
__device__ float g_bnsc[3][2 * Hh];
__device__ float g_xsum[Gg * Hh];
__device__ float g_cnt[Gg];
// padded W^T bf16 images: [layer][hi/lo][128 rows(n) * Pp cols(k)]
__device__ __nv_bfloat16 g_wt[3][2][IMG];

// ---------------- zero / degree / dinv ----------------
__global__ void k_zero_pre() {
    int i = blockIdx.x * blockDim.x + threadIdx.x;
    if (i < Nn) { g_deg[i] = 0; g_cursor[i] = 0; }
    if (i < Gg * Hh) g_xsum[i] = 0.0f;
    if (i < Gg) g_cnt[i] = 0.0f;
    if (i < 3 * BN_REP * 2 * Hh) ((float*)g_bnsum)[i] = 0.0f;
}

__global__ void k_deg(const int* __restrict__ dst) {
    int e = blockIdx.x * blockDim.x + threadIdx.x;
    if (e < Ee) atomicAdd(&g_deg[dst[e]], 1);
}

__global__ void k_dinv() {
    int i = blockIdx.x * blockDim.x + threadIdx.x;
    if (i < Nn) g_dinv[i] = rsqrtf((float)g_deg[i] + 1.0f);
}

// ---- W split: fp32 W[k][n] -> padded bf16 hi/lo images of W^T[n][k] ----
__global__ void k_wsplit(const float* __restrict__ W1, const float* __restrict__ W2,
                         const float* __restrict__ W3) {
    const float* Ws = (blockIdx.y == 0) ? W1 : (blockIdx.y == 1) ? W2 : W3;
    int n = blockIdx.x;          // 0..127
    int k = threadIdx.x;         // 0..127
    float v = Ws[k * 128 + n];
    __nv_bfloat16 hi = __float2bfloat16(v);
    float lo = v - __bfloat162float(hi);
    g_wt[blockIdx.y][0][n * Pp + k] = hi;
    g_wt[blockIdx.y][1][n * Pp + k] = __float2bfloat16(lo);
}

// ---------------- exclusive scan of degrees -> CSR offsets ----------------
__global__ void k_scan1() {
    __shared__ int s[SCAN_BS];
    int tid = threadIdx.x;
    int i = blockIdx.x * SCAN_BS + tid;
    int v = (i < Nn) ? g_deg[i] : 0;
    s[tid] = v;
    __syncthreads();
    for (int d = 1; d < SCAN_BS; d <<= 1) {
        int t = (tid >= d) ? s[tid - d] : 0;
        __syncthreads();
        s[tid] += t;
        __syncthreads();
    }
    if (i < Nn) g_off[i] = s[tid] - v;
    if (tid == SCAN_BS - 1) g_bsum[blockIdx.x] = s[tid];
}

__global__ void k_scan2() {
    __shared__ int s[128];
    int tid = threadIdx.x;
    int v = (tid < NBLK) ? g_bsum[tid] : 0;
    s[tid] = v;
    __syncthreads();
    for (int d = 1; d < 128; d <<= 1) {
        int t = (tid >= d) ? s[tid - d] : 0;
        __syncthreads();
        s[tid] += t;
        __syncthreads();
    }
    g_bsum[tid] = s[tid] - v;
}

__global__ void k_scan3() {
    int i = blockIdx.x * blockDim.x + threadIdx.x;
    if (i < Nn) g_off[i] += g_bsum[i >> 10];
    if (i == 0) g_off[Nn] = Ee;
}

__global__ void k_fill(const int* __restrict__ src, const int* __restrict__ dst) {
    int e = blockIdx.x * blockDim.x + threadIdx.x;
    if (e >= Ee) return;
    int d = dst[e];
    int s = src[e];
    int pos = g_off[d] + atomicAdd(&g_cursor[d], 1);
    g_csr[pos] = make_int2(s, __float_as_int(g_dinv[s] * g_dinv[d]));
}

// ---- tensor GEMM via mma.sync: g_h[M,128] = A[M,128] @ W[128,128] ----
// bf16 hi/lo split, 3 products. Fused BN apply on A load.
// mode 0: A = Ain; mode 1: A = relu(bn(g_agg)) -> also g_act;
// mode 2: A = relu(bn(g_agg)) + g_act -> also g_act
__global__ __launch_bounds__(256)
void gemm_tc(const float* __restrict__ Ain, int layer, int M, int mode, int bnidx) {
    extern __shared__ char sm[];
    int tid = threadIdx.x;
    int wid = tid >> 5;
    int lane = tid & 31;
    int gid = lane >> 2;     // 0..7
    int tig = lane & 3;      // 0..3
    int row0 = blockIdx.x * 128;

    // copy precomputed W^T hi+lo images (69632 B contiguous)
    {
        const uint4* wsrc = (const uint4*)(&g_wt[layer][0][0]);
        uint4* wdst = (uint4*)(sm + SM_WHI);
#pragma unroll
        for (int i = 0; i < 17; i++) wdst[tid + i * 256] = wsrc[tid + i * 256];
    }

    // A prologue: fp32 row-half -> (optional BN+ReLU+residual) -> bf16 hi/lo to smem
    {
        int r = tid & 127;
        int half = tid >> 7;
        int gr = row0 + r;
#pragma unroll
        for (int j = 0; j < 8; j++) {
            int k0 = half * 64 + j * 8;
            float4 va = make_float4(0.f, 0.f, 0.f, 0.f), vb = va;
            if (gr < M) {
                if (mode == 0) {
                    const float4* ap = (const float4*)(Ain + (size_t)gr * 128 + k0);
                    va = ap[0]; vb = ap[1];
                } else {
                    const float4* ap = (const float4*)(g_agg + (size_t)gr * 128 + k0);
                    float4 a0 = ap[0], a1 = ap[1];
                    const float4* scp = (const float4*)(g_bnsc[bnidx] + k0);
                    const float4* shp = (const float4*)(g_bnsc[bnidx] + 128 + k0);
                    float4 s0 = scp[0], s1 = scp[1], h0 = shp[0], h1 = shp[1];
                    va.x = fmaxf(fmaf(a0.x, s0.x, h0.x), 0.f);
                    va.y = fmaxf(fmaf(a0.y, s0.y, h0.y), 0.f);
                    va.z = fmaxf(fmaf(a0.z, s0.z, h0.z), 0.f);
                    va.w = fmaxf(fmaf(a0.w, s0.w, h0.w), 0.f);
                    vb.x = fmaxf(fmaf(a1.x, s1.x, h1.x), 0.f);
                    vb.y = fmaxf(fmaf(a1.y, s1.y, h1.y), 0.f);
                    vb.z = fmaxf(fmaf(a1.z, s1.z, h1.z), 0.f);
                    vb.w = fmaxf(fmaf(a1.w, s1.w, h1.w), 0.f);
                    if (mode == 2) {
                        const float4* rp = (const float4*)(g_act + (size_t)gr * 128 + k0);
                        float4 r0 = rp[0], r1 = rp[1];
                        va.x += r0.x; va.y += r0.y; va.z += r0.z; va.w += r0.w;
                        vb.x += r1.x; vb.y += r1.y; vb.z += r1.z; vb.w += r1.w;
                    }
                    float4* op = (float4*)(g_act + (size_t)gr * 128 + k0);
                    op[0] = va; op[1] = vb;
                }
            }
            float vv[8] = {va.x, va.y, va.z, va.w, vb.x, vb.y, vb.z, vb.w};
            uint32_t hw[4], lw[4];
#pragma unroll
            for (int q = 0; q < 4; q++) {
                __nv_bfloat162 hb = __floats2bfloat162_rn(vv[2 * q], vv[2 * q + 1]);
                float ra = __bfloat162float(hb.x), rb = __bfloat162float(hb.y);
                __nv_bfloat162 lb = __floats2bfloat162_rn(vv[2 * q] - ra, vv[2 * q + 1] - rb);
                hw[q] = *(uint32_t*)&hb;
                lw[q] = *(uint32_t*)&lb;
            }
            size_t off = ((size_t)r * Pp + k0) * 2;
            *(uint4*)(sm + SM_AHI + off) = make_uint4(hw[0], hw[1], hw[2], hw[3]);
            *(uint4*)(sm + SM_ALO + off) = make_uint4(lw[0], lw[1], lw[2], lw[3]);
        }
    }
    __syncthreads();

    // main loop: warp wid owns rows [wid*16, wid*16+16), 16 n-tiles of 8 cols
    int m0 = wid * 16;
    float acc[16][4];
#pragma unroll
    for (int nt = 0; nt < 16; nt++) {
        acc[nt][0] = 0.f; acc[nt][1] = 0.f; acc[nt][2] = 0.f; acc[nt][3] = 0.f;
    }

    int rl = m0 + gid, rh = rl + 8;
#pragma unroll 1
    for (int kc = 0; kc < 8; kc++) {
        int k0 = kc * 16;
        uint32_t ah[4], al[4];
        {
            size_t o0 = ((size_t)rl * Pp + k0 + tig * 2) * 2;
            size_t o1 = ((size_t)rh * Pp + k0 + tig * 2) * 2;
            ah[0] = *(const uint32_t*)(sm + SM_AHI + o0);
            ah[1] = *(const uint32_t*)(sm + SM_AHI + o1);
            ah[2] = *(const uint32_t*)(sm + SM_AHI + o0 + 16);
            ah[3] = *(const uint32_t*)(sm + SM_AHI + o1 + 16);
            al[0] = *(const uint32_t*)(sm + SM_ALO + o0);
            al[1] = *(const uint32_t*)(sm + SM_ALO + o1);
            al[2] = *(const uint32_t*)(sm + SM_ALO + o0 + 16);
            al[3] = *(const uint32_t*)(sm + SM_ALO + o1 + 16);
        }
#pragma unroll
        for (int nt = 0; nt < 16; nt++) {
            size_t bo = ((size_t)(nt * 8 + gid) * Pp + k0 + tig * 2) * 2;
            uint32_t bh0 = *(const uint32_t*)(sm + SM_WHI + bo);
            uint32_t bh1 = *(const uint32_t*)(sm + SM_WHI + bo + 16);
            uint32_t bl0 = *(const uint32_t*)(sm + SM_WLO + bo);
            uint32_t bl1 = *(const uint32_t*)(sm + SM_WLO + bo + 16);
            MMA_BF16(acc[nt], ah, bh0, bh1);
            MMA_BF16(acc[nt], ah, bl0, bl1);
            MMA_BF16(acc[nt], al, bh0, bh1);
        }
    }

    // epilogue: D frag (gid,2*tig) / (gid+8,2*tig)
    int gr1 = row0 + m0 + gid;
    int gr2 = gr1 + 8;
#pragma unroll
    for (int nt = 0; nt < 16; nt++) {
        int col = nt * 8 + tig * 2;
        if (gr1 < M) *(float2*)(g_h + (size_t)gr1 * 128 + col) = make_float2(acc[nt][0], acc[nt][1]);
        if (gr2 < M) *(float2*)(g_h + (size_t)gr2 * 128 + col) = make_float2(acc[nt][2], acc[nt][3]);
    }
}

// ------- gather + bias + fused BN partial stats -------
__global__ __launch_bounds__(512) void k_gather(const float* __restrict__ bias, int bnidx) {
    __shared__ float ss[16 * 128];

    int tid = threadIdx.x;
    int wloc = tid >> 5;
    int lane = tid & 31;
    int wid = blockIdx.x * 16 + wloc;

    int beg = g_off[wid];
    int end = g_off[wid + 1];
    float di = g_dinv[wid];
    float d2 = di * di;

    const float4* hv = (const float4*)g_h;
    float4 hs = hv[(size_t)wid * 32 + lane];
    float4 acc = make_float4(hs.x * d2, hs.y * d2, hs.z * d2, hs.w * d2);

    const int2* csr = g_csr;
    for (int e = beg; e < end; e++) {
        int2 c = csr[e];
        float w = __int_as_float(c.y);
        float4 v = hv[(size_t)c.x * 32 + lane];
        acc.x = fmaf(v.x, w, acc.x);
        acc.y = fmaf(v.y, w, acc.y);
        acc.z = fmaf(v.z, w, acc.z);
        acc.w = fmaf(v.w, w, acc.w);
    }

    float4 b4 = ((const float4*)bias)[lane];
    acc.x += b4.x; acc.y += b4.y; acc.z += b4.z; acc.w += b4.w;
    ((float4*)g_agg)[(size_t)wid * 32 + lane] = acc;

    int base = wloc * 128 + lane * 4;
    ss[base + 0] = acc.x; ss[base + 1] = acc.y; ss[base + 2] = acc.z; ss[base + 3] = acc.w;
    __syncthreads();

    if (tid < 256) {
        int c = tid & 127;
        int part = tid >> 7;
        float r = 0.f;
        if (part == 0) {
#pragma unroll
            for (int w = 0; w < 16; w++) r += ss[w * 128 + c];
        } else {
#pragma unroll
            for (int w = 0; w < 16; w++) { float v = ss[w * 128 + c]; r = fmaf(v, v, r); }
        }
        atomicAdd(&g_bnsum[bnidx][blockIdx.x & (BN_REP - 1)][part * 128 + c], r);
    }
}

// ---------------- batchnorm finalize ----------------
__global__ void k_bnfin(const float* __restrict__ g, const float* __restrict__ be, int bnidx) {
    int c = threadIdx.x;
    float s = 0.f, q = 0.f;
#pragma unroll
    for (int r = 0; r < BN_REP; r++) {
        s += g_bnsum[bnidx][r][c];
        q += g_bnsum[bnidx][r][128 + c];
    }
    float mean = s * (1.0f / (float)Nn);
    float var = q * (1.0f / (float)Nn) - mean * mean;
    float sc = g[c] * rsqrtf(var + EPSf);
    g_bnsc[bnidx][c] = sc;
    g_bnsc[bnidx][128 + c] = be[c] - mean * sc;
}

// ---------------- pooling with fused layer-3 BN apply ----------------
#define PCHUNK 512
__global__ void k_pool(const int* __restrict__ batch) {
    int c = threadIdx.x;
    int start = blockIdx.x * PCHUNK;
    if (start >= Nn) return;
    int end = min(start + PCHUNK, Nn);
    float sc = g_bnsc[2][c];
    float sh = g_bnsc[2][128 + c];
    float acc = 0.f, ccnt = 0.f;
    int gp = batch[start];
    for (int n = start; n < end; n++) {
        int g = batch[n];
        if (g != gp) {
            atomicAdd(&g_xsum[gp * 128 + c], acc);
            if (c == 0) atomicAdd(&g_cnt[gp], ccnt);
            acc = 0.f; ccnt = 0.f; gp = g;
        }
        float a = g_agg[(size_t)n * 128 + c];
        float v = fmaxf(fmaf(a, sc, sh), 0.f) + g_act[(size_t)n * 128 + c];
        acc += v;
        ccnt += 1.f;
    }
    atomicAdd(&g_xsum[gp * 128 + c], acc);
    if (c == 0) atomicAdd(&g_cnt[gp], ccnt);
}

// ---------------- MLP head ----------------
__global__ void k_mlp(const float* __restrict__ Wm1, const float* __restrict__ bm1,
                      const float* __restrict__ Wm2, const float* __restrict__ bm2,
                      float* __restrict__ out) {
    __shared__ float zs[128], zm[128], hid[128];
    int g = blockIdx.x, c = threadIdx.x;
    float cnt = fmaxf(g_cnt[g], 1.0f);
    float xs = g_xsum[g * 128 + c];
    zs[c] = xs;
    zm[c] = xs / cnt;
    __syncthreads();
    float acc = bm1[c];
#pragma unroll 8
    for (int k = 0; k < 128; k++)
        acc += zs[k] * Wm1[k * 128 + c] + zm[k] * Wm1[(128 + k) * 128 + c];
    hid[c] = fmaxf(acc, 0.f) * Wm2[c];
    __syncthreads();
    for (int s = 64; s > 0; s >>= 1) {
        if (c < s) hid[c] += hid[c + s];
        __syncthreads();
    }
    if (c == 0) out[g] = hid[0] + bm2[0];
}

// ---------------- host ----------------
extern "C" void kernel_launch(void* const* d_in, const int* in_sizes, int n_in,
                              void* d_out, int out_size) {
    const float *x, *W1, *b1, *W2, *b2, *W3, *b3;
    const float *g1, *be1, *g2, *be2, *g3, *be3;
    const float *Wm1, *bm1, *Wm2, *bm2;
    const int *ei, *batch;

    if (in_sizes[1] == 2 * Ee) {
        x   = (const float*)d_in[0];
        ei  = (const int*)  d_in[1];
        batch = (const int*)d_in[2];
        W1 = (const float*)d_in[3];  b1 = (const float*)d_in[4];
        W2 = (const float*)d_in[5];  b2 = (const float*)d_in[6];
        W3 = (const float*)d_in[7];  b3 = (const float*)d_in[8];
        g1 = (const float*)d_in[9];  be1 = (const float*)d_in[10];
        g2 = (const float*)d_in[11]; be2 = (const float*)d_in[12];
        g3 = (const float*)d_in[13]; be3 = (const float*)d_in[14];
        Wm1 = (const float*)d_in[15]; bm1 = (const float*)d_in[16];
        Wm2 = (const float*)d_in[17]; bm2 = (const float*)d_in[18];
    } else {
        x   = (const float*)d_in[0];
        W1 = (const float*)d_in[1];  b1 = (const float*)d_in[2];
        g1 = (const float*)d_in[3];  be1 = (const float*)d_in[4];
        W2 = (const float*)d_in[5];  b2 = (const float*)d_in[6];
        g2 = (const float*)d_in[7];  be2 = (const float*)d_in[8];
        W3 = (const float*)d_in[9];  b3 = (const float*)d_in[10];
        g3 = (const float*)d_in[11]; be3 = (const float*)d_in[12];
        Wm1 = (const float*)d_in[13]; bm1 = (const float*)d_in[14];
        Wm2 = (const float*)d_in[15]; bm2 = (const float*)d_in[16];
        ei  = (const int*)d_in[17];
        batch = (const int*)d_in[18];
    }

    const int* src = ei;
    const int* dst = ei + Ee;
    float* out = (float*)d_out;

    cudaFuncSetAttribute(gemm_tc, cudaFuncAttributeMaxDynamicSharedMemorySize, SM_TOTAL);

    const int ZB = (Nn + 255) / 256;          // 391
    const int EB = (Ee + 255) / 256;          // 6250
    const int GEMMB = (Nn + 127) / 128;       // 782
    const int GATB = (Nn + 15) / 16;          // 6250
    const int POOLB = (Nn + PCHUNK - 1) / PCHUNK;

    // launches 1-3
    k_zero_pre<<<ZB, 256>>>();
    k_deg<<<EB, 256>>>(dst);
    k_wsplit<<<dim3(128, 3), 128>>>(W1, W2, W3);

    // launch 4: layer-1 tensor GEMM (profiling slot)
    gemm_tc<<<GEMMB, 256, SM_TOTAL>>>(x, 0, Nn, 0, 0);

    // CSR build
    k_dinv<<<ZB, 256>>>();
    k_scan1<<<NBLK, SCAN_BS>>>();
    k_scan2<<<1, 128>>>();
    k_scan3<<<ZB, 256>>>();
    k_fill<<<EB, 256>>>(src, dst);

    // layer 1 aggregate + BN stats
    k_gather<<<GATB, 512>>>(b1, 0);
    k_bnfin<<<1, 128>>>(g1, be1, 0);

    // layer 2: GEMM with fused BN1 apply, then aggregate
    gemm_tc<<<GEMMB, 256, SM_TOTAL>>>(nullptr, 1, Nn, 1, 0);
    k_gather<<<GATB, 512>>>(b2, 1);
    k_bnfin<<<1, 128>>>(g2, be2, 1);

    // layer 3: GEMM with fused BN2 apply + residual, then aggregate
    gemm_tc<<<GEMMB, 256, SM_TOTAL>>>(nullptr, 2, Nn, 2, 1);
    k_gather<<<GATB, 512>>>(b3, 2);
    k_bnfin<<<1, 128>>>(g3, be3, 2);

    // pooling (fused BN3 apply + residual) + MLP
    k_pool<<<POOLB, 128>>>(batch);
    k_mlp<<<Gg, 128>>>(Wm1, bm1, Wm2, bm2, out);
}

// round 7
// speedup vs baseline: 1.9555x; 1.1564x over previous
#include <cuda_runtime.h>
#include <cuda_bf16.h>
#include <cstdint>

#define Nn 100000
#define Ee 1600000
#define Hh 128
#define Gg 64
#define EPSf 1e-5f

#define SCAN_BS 1024
#define NBLK ((Nn + SCAN_BS - 1) / SCAN_BS)   // 98
#define BN_REP 4

// ---------------- mma GEMM smem layout (M=256 per block) ----------------
#define Pp 136                        // bf16 elements per row (padded; 272 B)
#define AIMG_B (256 * Pp * 2)         // 69632 B per A image
#define WIMG_B (128 * Pp * 2)         // 34816 B per W image
#define SM_AHI 0
#define SM_ALO AIMG_B
#define SM_W   (2 * AIMG_B)           // hi at +0, lo at +WIMG_B (contiguous in g_wt)
#define SM_BN  (2 * AIMG_B + 2 * WIMG_B)
#define SM_TOTAL (SM_BN + 1024)       // 209920 B

#define MMA_BF16(d, a, b0, b1) \
    asm volatile("mma.sync.aligned.m16n8k16.row.col.f32.bf16.bf16.f32 " \
        "{%0,%1,%2,%3}, {%4,%5,%6,%7}, {%8,%9}, {%0,%1,%2,%3};" \
        : "+f"((d)[0]), "+f"((d)[1]), "+f"((d)[2]), "+f"((d)[3]) \
        : "r"((a)[0]), "r"((a)[1]), "r"((a)[2]), "r"((a)[3]), "r"(b0), "r"(b1))

// ---------------- device scratch ----------------
__device__ int   g_deg[Nn];
__device__ float g_dinv[Nn];
__device__ int   g_off[Nn + 1];
__device__ int   g_cursor[Nn];
__device__ int   g_bsum[SCAN_BS];
__device__ int2  g_csr[Ee];
__device__ float g_h[(size_t)Nn * Hh];
__device__ float g_agg[(size_t)Nn * Hh];
__device__ float g_act[(size_t)Nn * Hh];
__device__ float g_bnsum[3][BN_REP][2 * Hh];
__device__ float g_xsum[Gg * Hh];
__device__ float g_cnt[Gg];
// padded W^T bf16 images: [layer][hi/lo][128 rows(n) * Pp cols(k)]
__device__ __nv_bfloat16 g_wt[3][2][128 * Pp];

// ---------------- zero / degree ----------------
__global__ void k_zero_pre() {
    int i = blockIdx.x * blockDim.x + threadIdx.x;
    if (i < Nn) { g_deg[i] = 0; g_cursor[i] = 0; }
    if (i < Gg * Hh) g_xsum[i] = 0.0f;
    if (i < Gg) g_cnt[i] = 0.0f;
    if (i < 3 * BN_REP * 2 * Hh) ((float*)g_bnsum)[i] = 0.0f;
}

__global__ void k_deg(const int* __restrict__ dst) {
    int e = blockIdx.x * blockDim.x + threadIdx.x;
    if (e < Ee) atomicAdd(&g_deg[dst[e]], 1);
}

// ---- W split: fp32 W[k][n] -> padded bf16 hi/lo images of W^T[n][k] ----
__global__ void k_wsplit(const float* __restrict__ W1, const float* __restrict__ W2,
                         const float* __restrict__ W3) {
    const float* Ws = (blockIdx.y == 0) ? W1 : (blockIdx.y == 1) ? W2 : W3;
    int n = blockIdx.x;          // 0..127
    int k = threadIdx.x;         // 0..127
    float v = Ws[k * 128 + n];
    __nv_bfloat16 hi = __float2bfloat16(v);
    float lo = v - __bfloat162float(hi);
    g_wt[blockIdx.y][0][n * Pp + k] = hi;
    g_wt[blockIdx.y][1][n * Pp + k] = __float2bfloat16(lo);
}

// ---------------- exclusive scan of degrees -> CSR offsets ----------------
__global__ void k_scan1() {
    __shared__ int s[SCAN_BS];
    int tid = threadIdx.x;
    int i = blockIdx.x * SCAN_BS + tid;
    int v = (i < Nn) ? g_deg[i] : 0;
    s[tid] = v;
    __syncthreads();
    for (int d = 1; d < SCAN_BS; d <<= 1) {
        int t = (tid >= d) ? s[tid - d] : 0;
        __syncthreads();
        s[tid] += t;
        __syncthreads();
    }
    if (i < Nn) g_off[i] = s[tid] - v;
    if (tid == SCAN_BS - 1) g_bsum[blockIdx.x] = s[tid];
}

__global__ void k_scan2() {
    __shared__ int s[128];
    int tid = threadIdx.x;
    int v = (tid < NBLK) ? g_bsum[tid] : 0;
    s[tid] = v;
    __syncthreads();
    for (int d = 1; d < 128; d <<= 1) {
        int t = (tid >= d) ? s[tid - d] : 0;
        __syncthreads();
        s[tid] += t;
        __syncthreads();
    }
    g_bsum[tid] = s[tid] - v;
}

__global__ void k_scan3() {   // + fused dinv
    int i = blockIdx.x * blockDim.x + threadIdx.x;
    if (i < Nn) {
        g_off[i] += g_bsum[i >> 10];
        g_dinv[i] = rsqrtf((float)g_deg[i] + 1.0f);
    }
    if (i == 0) g_off[Nn] = Ee;
}

__global__ void k_fill(const int* __restrict__ src, const int* __restrict__ dst) {
    int e = blockIdx.x * blockDim.x + threadIdx.x;
    if (e >= Ee) return;
    int d = dst[e];
    int s = src[e];
    int pos = g_off[d] + atomicAdd(&g_cursor[d], 1);
    g_csr[pos] = make_int2(s, __float_as_int(g_dinv[s] * g_dinv[d]));
}

// ---- tensor GEMM via mma.sync: g_h[M,128] = A[M,128] @ W[128,128] ----
// 512 threads, 256 rows per block. bf16 hi/lo split, 3 products.
// mode 0: A = Ain; mode 1: A = relu(bn(g_agg)) -> also g_act;
// mode 2: A = relu(bn(g_agg)) + g_act -> also g_act
__global__ __launch_bounds__(512)
void gemm_tc(const float* __restrict__ Ain, int layer, int M, int mode, int bnidx,
             const float* __restrict__ gam, const float* __restrict__ bet) {
    extern __shared__ char sm[];
    float* s_bn = (float*)(sm + SM_BN);
    int tid = threadIdx.x;
    int wid = tid >> 5;
    int lane = tid & 31;
    int gid = lane >> 2;     // 0..7
    int tig = lane & 3;      // 0..3
    int row0 = blockIdx.x * 256;

    // copy precomputed W^T hi+lo images (69632 B contiguous)
    {
        const uint4* wsrc = (const uint4*)(&g_wt[layer][0][0]);
        uint4* wdst = (uint4*)(sm + SM_W);
        for (int i = tid; i < 4352; i += 512) wdst[i] = wsrc[i];
    }

    // per-block BN scale/shift recompute (replaces k_bnfin)
    if (mode) {
        if (tid < 128) {
            float s = 0.f, q = 0.f;
#pragma unroll
            for (int r = 0; r < BN_REP; r++) {
                s += g_bnsum[bnidx][r][tid];
                q += g_bnsum[bnidx][r][128 + tid];
            }
            float mean = s * (1.0f / (float)Nn);
            float var = q * (1.0f / (float)Nn) - mean * mean;
            float sc = gam[tid] * rsqrtf(var + EPSf);
            s_bn[tid] = sc;
            s_bn[128 + tid] = bet[tid] - mean * sc;
        }
        __syncthreads();
    }

    // A prologue: 512 threads cover 256 rows x 2 halves
    {
        int r = tid & 255;
        int half = tid >> 8;
        int gr = row0 + r;
#pragma unroll
        for (int j = 0; j < 8; j++) {
            int k0 = half * 64 + j * 8;
            float4 va = make_float4(0.f, 0.f, 0.f, 0.f), vb = va;
            if (gr < M) {
                if (mode == 0) {
                    const float4* ap = (const float4*)(Ain + (size_t)gr * 128 + k0);
                    va = ap[0]; vb = ap[1];
                } else {
                    const float4* ap = (const float4*)(g_agg + (size_t)gr * 128 + k0);
                    float4 a0 = ap[0], a1 = ap[1];
                    const float4* scp = (const float4*)(s_bn + k0);
                    const float4* shp = (const float4*)(s_bn + 128 + k0);
                    float4 s0 = scp[0], s1 = scp[1], h0 = shp[0], h1 = shp[1];
                    va.x = fmaxf(fmaf(a0.x, s0.x, h0.x), 0.f);
                    va.y = fmaxf(fmaf(a0.y, s0.y, h0.y), 0.f);
                    va.z = fmaxf(fmaf(a0.z, s0.z, h0.z), 0.f);
                    va.w = fmaxf(fmaf(a0.w, s0.w, h0.w), 0.f);
                    vb.x = fmaxf(fmaf(a1.x, s1.x, h1.x), 0.f);
                    vb.y = fmaxf(fmaf(a1.y, s1.y, h1.y), 0.f);
                    vb.z = fmaxf(fmaf(a1.z, s1.z, h1.z), 0.f);
                    vb.w = fmaxf(fmaf(a1.w, s1.w, h1.w), 0.f);
                    if (mode == 2) {
                        const float4* rp = (const float4*)(g_act + (size_t)gr * 128 + k0);
                        float4 r0 = rp[0], r1 = rp[1];
                        va.x += r0.x; va.y += r0.y; va.z += r0.z; va.w += r0.w;
                        vb.x += r1.x; vb.y += r1.y; vb.z += r1.z; vb.w += r1.w;
                    }
                    float4* op = (float4*)(g_act + (size_t)gr * 128 + k0);
                    op[0] = va; op[1] = vb;
                }
            }
            float vv[8] = {va.x, va.y, va.z, va.w, vb.x, vb.y, vb.z, vb.w};
            uint32_t hw[4], lw[4];
#pragma unroll
            for (int q = 0; q < 4; q++) {
                __nv_bfloat162 hb = __floats2bfloat162_rn(vv[2 * q], vv[2 * q + 1]);
                float ra = __bfloat162float(hb.x), rb = __bfloat162float(hb.y);
                __nv_bfloat162 lb = __floats2bfloat162_rn(vv[2 * q] - ra, vv[2 * q + 1] - rb);
                hw[q] = *(uint32_t*)&hb;
                lw[q] = *(uint32_t*)&lb;
            }
            size_t off = ((size_t)r * Pp + k0) * 2;
            *(uint4*)(sm + SM_AHI + off) = make_uint4(hw[0], hw[1], hw[2], hw[3]);
            *(uint4*)(sm + SM_ALO + off) = make_uint4(lw[0], lw[1], lw[2], lw[3]);
        }
    }
    __syncthreads();

    // main loop: 16 warps, warp wid owns rows [wid*16, wid*16+16), 16 n-tiles
    int m0 = wid * 16;
    float acc[16][4];
#pragma unroll
    for (int nt = 0; nt < 16; nt++) {
        acc[nt][0] = 0.f; acc[nt][1] = 0.f; acc[nt][2] = 0.f; acc[nt][3] = 0.f;
    }

    int rl = m0 + gid, rh = rl + 8;
#pragma unroll 1
    for (int kc = 0; kc < 8; kc++) {
        int k0 = kc * 16;
        uint32_t ah[4], al[4];
        {
            size_t o0 = ((size_t)rl * Pp + k0 + tig * 2) * 2;
            size_t o1 = ((size_t)rh * Pp + k0 + tig * 2) * 2;
            ah[0] = *(const uint32_t*)(sm + SM_AHI + o0);
            ah[1] = *(const uint32_t*)(sm + SM_AHI + o1);
            ah[2] = *(const uint32_t*)(sm + SM_AHI + o0 + 16);
            ah[3] = *(const uint32_t*)(sm + SM_AHI + o1 + 16);
            al[0] = *(const uint32_t*)(sm + SM_ALO + o0);
            al[1] = *(const uint32_t*)(sm + SM_ALO + o1);
            al[2] = *(const uint32_t*)(sm + SM_ALO + o0 + 16);
            al[3] = *(const uint32_t*)(sm + SM_ALO + o1 + 16);
        }
#pragma unroll
        for (int nt = 0; nt < 16; nt++) {
            size_t bo = ((size_t)(nt * 8 + gid) * Pp + k0 + tig * 2) * 2;
            uint32_t bh0 = *(const uint32_t*)(sm + SM_W + bo);
            uint32_t bh1 = *(const uint32_t*)(sm + SM_W + bo + 16);
            uint32_t bl0 = *(const uint32_t*)(sm + SM_W + WIMG_B + bo);
            uint32_t bl1 = *(const uint32_t*)(sm + SM_W + WIMG_B + bo + 16);
            MMA_BF16(acc[nt], ah, bh0, bh1);
            MMA_BF16(acc[nt], ah, bl0, bl1);
            MMA_BF16(acc[nt], al, bh0, bh1);
        }
    }

    // epilogue
    int gr1 = row0 + m0 + gid;
    int gr2 = gr1 + 8;
#pragma unroll
    for (int nt = 0; nt < 16; nt++) {
        int col = nt * 8 + tig * 2;
        if (gr1 < M) *(float2*)(g_h + (size_t)gr1 * 128 + col) = make_float2(acc[nt][0], acc[nt][1]);
        if (gr2 < M) *(float2*)(g_h + (size_t)gr2 * 128 + col) = make_float2(acc[nt][2], acc[nt][3]);
    }
}

// ------- gather + bias + fused BN partial stats (2-edge unrolled) -------
__global__ __launch_bounds__(512) void k_gather(const float* __restrict__ bias, int bnidx) {
    __shared__ float ss[16 * 128];

    int tid = threadIdx.x;
    int wloc = tid >> 5;
    int lane = tid & 31;
    int wid = blockIdx.x * 16 + wloc;

    int beg = g_off[wid];
    int end = g_off[wid + 1];
    float di = g_dinv[wid];
    float d2 = di * di;

    const float4* hv = (const float4*)g_h;
    float4 hs = hv[(size_t)wid * 32 + lane];
    float4 acc = make_float4(hs.x * d2, hs.y * d2, hs.z * d2, hs.w * d2);
    float4 acc2 = make_float4(0.f, 0.f, 0.f, 0.f);

    const int2* csr = g_csr;
    int e = beg;
    for (; e + 2 <= end; e += 2) {
        int2 c0 = csr[e];
        int2 c1 = csr[e + 1];
        float4 v0 = hv[(size_t)c0.x * 32 + lane];
        float4 v1 = hv[(size_t)c1.x * 32 + lane];
        float w0 = __int_as_float(c0.y);
        float w1 = __int_as_float(c1.y);
        acc.x = fmaf(v0.x, w0, acc.x);
        acc.y = fmaf(v0.y, w0, acc.y);
        acc.z = fmaf(v0.z, w0, acc.z);
        acc.w = fmaf(v0.w, w0, acc.w);
        acc2.x = fmaf(v1.x, w1, acc2.x);
        acc2.y = fmaf(v1.y, w1, acc2.y);
        acc2.z = fmaf(v1.z, w1, acc2.z);
        acc2.w = fmaf(v1.w, w1, acc2.w);
    }
    if (e < end) {
        int2 c = csr[e];
        float w = __int_as_float(c.y);
        float4 v = hv[(size_t)c.x * 32 + lane];
        acc.x = fmaf(v.x, w, acc.x);
        acc.y = fmaf(v.y, w, acc.y);
        acc.z = fmaf(v.z, w, acc.z);
        acc.w = fmaf(v.w, w, acc.w);
    }
    acc.x += acc2.x; acc.y += acc2.y; acc.z += acc2.z; acc.w += acc2.w;

    float4 b4 = ((const float4*)bias)[lane];
    acc.x += b4.x; acc.y += b4.y; acc.z += b4.z; acc.w += b4.w;
    ((float4*)g_agg)[(size_t)wid * 32 + lane] = acc;

    int base = wloc * 128 + lane * 4;
    ss[base + 0] = acc.x; ss[base + 1] = acc.y; ss[base + 2] = acc.z; ss[base + 3] = acc.w;
    __syncthreads();

    if (tid < 256) {
        int c = tid & 127;
        int part = tid >> 7;
        float r = 0.f;
        if (part == 0) {
#pragma unroll
            for (int w = 0; w < 16; w++) r += ss[w * 128 + c];
        } else {
#pragma unroll
            for (int w = 0; w < 16; w++) { float v = ss[w * 128 + c]; r = fmaf(v, v, r); }
        }
        atomicAdd(&g_bnsum[bnidx][blockIdx.x & (BN_REP - 1)][part * 128 + c], r);
    }
}

// ---------------- pooling with fused layer-3 BN finalize+apply ----------------
#define PCHUNK 256
__global__ void k_pool(const int* __restrict__ batch,
                       const float* __restrict__ gam, const float* __restrict__ bet) {
    int c = threadIdx.x;
    // recompute BN3 scale/shift (replaces k_bnfin)
    float s = 0.f, q = 0.f;
#pragma unroll
    for (int r = 0; r < BN_REP; r++) {
        s += g_bnsum[2][r][c];
        q += g_bnsum[2][r][128 + c];
    }
    float mean = s * (1.0f / (float)Nn);
    float var = q * (1.0f / (float)Nn) - mean * mean;
    float sc = gam[c] * rsqrtf(var + EPSf);
    float sh = bet[c] - mean * sc;

    int start = blockIdx.x * PCHUNK;
    if (start >= Nn) return;
    int end = min(start + PCHUNK, Nn);
    float acc = 0.f, ccnt = 0.f;
    int gp = batch[start];
    for (int n = start; n < end; n++) {
        int g = batch[n];
        if (g != gp) {
            atomicAdd(&g_xsum[gp * 128 + c], acc);
            if (c == 0) atomicAdd(&g_cnt[gp], ccnt);
            acc = 0.f; ccnt = 0.f; gp = g;
        }
        float a = g_agg[(size_t)n * 128 + c];
        float v = fmaxf(fmaf(a, sc, sh), 0.f) + g_act[(size_t)n * 128 + c];
        acc += v;
        ccnt += 1.f;
    }
    atomicAdd(&g_xsum[gp * 128 + c], acc);
    if (c == 0) atomicAdd(&g_cnt[gp], ccnt);
}

// ---------------- MLP head ----------------
__global__ void k_mlp(const float* __restrict__ Wm1, const float* __restrict__ bm1,
                      const float* __restrict__ Wm2, const float* __restrict__ bm2,
                      float* __restrict__ out) {
    __shared__ float zs[128], zm[128], hid[128];
    int g = blockIdx.x, c = threadIdx.x;
    float cnt = fmaxf(g_cnt[g], 1.0f);
    float xs = g_xsum[g * 128 + c];
    zs[c] = xs;
    zm[c] = xs / cnt;
    __syncthreads();
    float acc = bm1[c];
#pragma unroll 8
    for (int k = 0; k < 128; k++)
        acc += zs[k] * Wm1[k * 128 + c] + zm[k] * Wm1[(128 + k) * 128 + c];
    hid[c] = fmaxf(acc, 0.f) * Wm2[c];
    __syncthreads();
    for (int s = 64; s > 0; s >>= 1) {
        if (c < s) hid[c] += hid[c + s];
        __syncthreads();
    }
    if (c == 0) out[g] = hid[0] + bm2[0];
}

// ---------------- host ----------------
extern "C" void kernel_launch(void* const* d_in, const int* in_sizes, int n_in,
                              void* d_out, int out_size) {
    const float *x, *W1, *b1, *W2, *b2, *W3, *b3;
    const float *g1, *be1, *g2, *be2, *g3, *be3;
    const float *Wm1, *bm1, *Wm2, *bm2;
    const int *ei, *batch;

    if (in_sizes[1] == 2 * Ee) {
        x   = (const float*)d_in[0];
        ei  = (const int*)  d_in[1];
        batch = (const int*)d_in[2];
        W1 = (const float*)d_in[3];  b1 = (const float*)d_in[4];
        W2 = (const float*)d_in[5];  b2 = (const float*)d_in[6];
        W3 = (const float*)d_in[7];  b3 = (const float*)d_in[8];
        g1 = (const float*)d_in[9];  be1 = (const float*)d_in[10];
        g2 = (const float*)d_in[11]; be2 = (const float*)d_in[12];
        g3 = (const float*)d_in[13]; be3 = (const float*)d_in[14];
        Wm1 = (const float*)d_in[15]; bm1 = (const float*)d_in[16];
        Wm2 = (const float*)d_in[17]; bm2 = (const float*)d_in[18];
    } else {
        x   = (const float*)d_in[0];
        W1 = (const float*)d_in[1];  b1 = (const float*)d_in[2];
        g1 = (const float*)d_in[3];  be1 = (const float*)d_in[4];
        W2 = (const float*)d_in[5];  b2 = (const float*)d_in[6];
        g2 = (const float*)d_in[7];  be2 = (const float*)d_in[8];
        W3 = (const float*)d_in[9];  b3 = (const float*)d_in[10];
        g3 = (const float*)d_in[11]; be3 = (const float*)d_in[12];
        Wm1 = (const float*)d_in[13]; bm1 = (const float*)d_in[14];
        Wm2 = (const float*)d_in[15]; bm2 = (const float*)d_in[16];
        ei  = (const int*)d_in[17];
        batch = (const int*)d_in[18];
    }

    const int* src = ei;
    const int* dst = ei + Ee;
    float* out = (float*)d_out;

    cudaFuncSetAttribute(gemm_tc, cudaFuncAttributeMaxDynamicSharedMemorySize, SM_TOTAL);

    const int ZB = (Nn + 255) / 256;          // 391
    const int EB = (Ee + 255) / 256;          // 6250
    const int GEMMB = (Nn + 255) / 256;       // 391 blocks x 512 threads
    const int GATB = (Nn + 15) / 16;          // 6250
    const int POOLB = (Nn + PCHUNK - 1) / PCHUNK;  // 391

    // launches 1-3
    k_zero_pre<<<ZB, 256>>>();
    k_deg<<<EB, 256>>>(dst);
    k_wsplit<<<dim3(128, 3), 128>>>(W1, W2, W3);

    // launch 4: layer-1 tensor GEMM (profiling slot)
    gemm_tc<<<GEMMB, 512, SM_TOTAL>>>(x, 0, Nn, 0, 0, nullptr, nullptr);

    // CSR build (dinv fused into scan3)
    k_scan1<<<NBLK, SCAN_BS>>>();
    k_scan2<<<1, 128>>>();
    k_scan3<<<ZB, 256>>>();
    k_fill<<<EB, 256>>>(src, dst);

    // layer 1 aggregate + BN stats
    k_gather<<<GATB, 512>>>(b1, 0);

    // layer 2: GEMM with fused BN1 finalize+apply, then aggregate
    gemm_tc<<<GEMMB, 512, SM_TOTAL>>>(nullptr, 1, Nn, 1, 0, g1, be1);
    k_gather<<<GATB, 512>>>(b2, 1);

    // layer 3: GEMM with fused BN2 finalize+apply + residual, then aggregate
    gemm_tc<<<GEMMB, 512, SM_TOTAL>>>(nullptr, 2, Nn, 2, 1, g2, be2);
    k_gather<<<GATB, 512>>>(b3, 2);

    // pooling (fused BN3 finalize+apply + residual) + MLP
    k_pool<<<POOLB, 128>>>(batch, g3, be3);
    k_mlp<<<Gg, 128>>>(Wm1, bm1, Wm2, bm2, out);
}

// round 8
// speedup vs baseline: 2.2379x; 1.1444x over previous
#include <cuda_runtime.h>
#include <cuda_bf16.h>
#include <cuda_fp16.h>
#include <cstdint>

#define Nn 100000
#define Ee 1600000
#define Hh 128
#define Gg 64
#define EPSf 1e-5f

#define SCAN_BS 1024
#define NBLK ((Nn + SCAN_BS - 1) / SCAN_BS)   // 98
#define BN_REP 4
#define DINVB ((Nn + 127) / 128)              // 782

// ---------------- mma GEMM smem layout (M=256 per block) ----------------
#define Pp 136                        // bf16 elements per row (padded; 272 B)
#define AIMG_B (256 * Pp * 2)         // 69632 B per A image
#define WIMG_B (128 * Pp * 2)         // 34816 B per W image
#define SM_AHI 0
#define SM_ALO AIMG_B
#define SM_W   (2 * AIMG_B)           // hi at +0, lo at +WIMG_B
#define SM_BN  (2 * AIMG_B + 2 * WIMG_B)
#define SM_TOTAL (SM_BN + 1024)       // 209920 B

#define MMA_BF16(d, a, b0, b1) \
    asm volatile("mma.sync.aligned.m16n8k16.row.col.f32.bf16.bf16.f32 " \
        "{%0,%1,%2,%3}, {%4,%5,%6,%7}, {%8,%9}, {%0,%1,%2,%3};" \
        : "+f"((d)[0]), "+f"((d)[1]), "+f"((d)[2]), "+f"((d)[3]) \
        : "r"((a)[0]), "r"((a)[1]), "r"((a)[2]), "r"((a)[3]), "r"(b0), "r"(b1))

// ---------------- device scratch ----------------
__device__ int   g_deg[Nn];
__device__ float g_dinv[Nn];
__device__ int   g_off[Nn + 1];
__device__ int   g_cursor[Nn];
__device__ int   g_bsum[SCAN_BS];
__device__ int   g_csr[Ee];                       // src only (weights folded into h')
__device__ __half g_h16[(size_t)Nn * Hh];         // h' = dinv * (A @ W), fp16
__device__ float g_agg[(size_t)Nn * Hh];
__device__ float g_act[(size_t)Nn * Hh];
__device__ float g_bnsum[3][BN_REP][2 * Hh];
__device__ float g_xsum[Gg * Hh];
__device__ float g_cnt[Gg];
__device__ __nv_bfloat16 g_wt[3][2][128 * Pp];    // padded W^T bf16 hi/lo images

// ---------------- zero / degree ----------------
__global__ void k_zero_pre() {
    int i = blockIdx.x * blockDim.x + threadIdx.x;
    if (i < Nn) { g_deg[i] = 0; g_cursor[i] = 0; }
    if (i < Gg * Hh) g_xsum[i] = 0.0f;
    if (i < Gg) g_cnt[i] = 0.0f;
    if (i < 3 * BN_REP * 2 * Hh) ((float*)g_bnsum)[i] = 0.0f;
}

__global__ void k_deg(const int* __restrict__ dst) {
    int e = blockIdx.x * blockDim.x + threadIdx.x;
    if (e < Ee) atomicAdd(&g_deg[dst[e]], 1);
}

// ---- prep: dinv (blocks [0,DINVB)) + W split (blocks [DINVB, DINVB+384)) ----
__global__ void k_prep(const float* __restrict__ W1, const float* __restrict__ W2,
                       const float* __restrict__ W3) {
    int b = blockIdx.x;
    if (b < DINVB) {
        int i = b * 128 + threadIdx.x;
        if (i < Nn) g_dinv[i] = rsqrtf((float)g_deg[i] + 1.0f);
    } else {
        int bi = b - DINVB;                 // 0..383
        int layer = bi >> 7;
        int n = bi & 127;
        const float* Ws = (layer == 0) ? W1 : (layer == 1) ? W2 : W3;
        int k = threadIdx.x;
        float v = Ws[k * 128 + n];
        __nv_bfloat16 hi = __float2bfloat16(v);
        float lo = v - __bfloat162float(hi);
        g_wt[layer][0][n * Pp + k] = hi;
        g_wt[layer][1][n * Pp + k] = __float2bfloat16(lo);
    }
}

// ---------------- exclusive scan of degrees -> CSR offsets ----------------
__global__ void k_scan1() {
    __shared__ int s[SCAN_BS];
    int tid = threadIdx.x;
    int i = blockIdx.x * SCAN_BS + tid;
    int v = (i < Nn) ? g_deg[i] : 0;
    s[tid] = v;
    __syncthreads();
    for (int d = 1; d < SCAN_BS; d <<= 1) {
        int t = (tid >= d) ? s[tid - d] : 0;
        __syncthreads();
        s[tid] += t;
        __syncthreads();
    }
    if (i < Nn) g_off[i] = s[tid] - v;
    if (tid == SCAN_BS - 1) g_bsum[blockIdx.x] = s[tid];
}

__global__ void k_scan2() {
    __shared__ int s[128];
    int tid = threadIdx.x;
    int v = (tid < NBLK) ? g_bsum[tid] : 0;
    s[tid] = v;
    __syncthreads();
    for (int d = 1; d < 128; d <<= 1) {
        int t = (tid >= d) ? s[tid - d] : 0;
        __syncthreads();
        s[tid] += t;
        __syncthreads();
    }
    g_bsum[tid] = s[tid] - v;
}

__global__ void k_scan3() {
    int i = blockIdx.x * blockDim.x + threadIdx.x;
    if (i < Nn) g_off[i] += g_bsum[i >> 10];
    if (i == 0) g_off[Nn] = Ee;
}

__global__ void k_fill(const int* __restrict__ src, const int* __restrict__ dst) {
    int e = blockIdx.x * blockDim.x + threadIdx.x;
    if (e >= Ee) return;
    int d = dst[e];
    int pos = g_off[d] + atomicAdd(&g_cursor[d], 1);
    g_csr[pos] = src[e];
}

// ---- tensor GEMM via mma.sync: g_h16[M,128] = fp16( dinv * (A @ W) ) ----
// 512 threads, 256 rows/block, warp tile 32x64. bf16 hi/lo, 3 products.
// mode 0: A = Ain; mode 1: A = relu(bn(g_agg)) -> also g_act;
// mode 2: A = relu(bn(g_agg)) + g_act -> also g_act
__global__ __launch_bounds__(512)
void gemm_tc(const float* __restrict__ Ain, int layer, int M, int mode, int bnidx,
             const float* __restrict__ gam, const float* __restrict__ bet) {
    extern __shared__ char sm[];
    float* s_bn = (float*)(sm + SM_BN);
    int tid = threadIdx.x;
    int wid = tid >> 5;
    int lane = tid & 31;
    int gid = lane >> 2;     // 0..7
    int tig = lane & 3;      // 0..3
    int row0 = blockIdx.x * 256;

    // copy W^T hi+lo images
    {
        const uint4* wsrc = (const uint4*)(&g_wt[layer][0][0]);
        uint4* wdst = (uint4*)(sm + SM_W);
        for (int i = tid; i < 4352; i += 512) wdst[i] = wsrc[i];
    }

    // per-block BN scale/shift recompute
    if (mode) {
        if (tid < 128) {
            float s = 0.f, q = 0.f;
#pragma unroll
            for (int r = 0; r < BN_REP; r++) {
                s += g_bnsum[bnidx][r][tid];
                q += g_bnsum[bnidx][r][128 + tid];
            }
            float mean = s * (1.0f / (float)Nn);
            float var = q * (1.0f / (float)Nn) - mean * mean;
            float sc = gam[tid] * rsqrtf(var + EPSf);
            s_bn[tid] = sc;
            s_bn[128 + tid] = bet[tid] - mean * sc;
        }
        __syncthreads();
    }

    // A prologue
    {
        int r = tid & 255;
        int half = tid >> 8;
        int gr = row0 + r;
#pragma unroll
        for (int j = 0; j < 8; j++) {
            int k0 = half * 64 + j * 8;
            float4 va = make_float4(0.f, 0.f, 0.f, 0.f), vb = va;
            if (gr < M) {
                if (mode == 0) {
                    const float4* ap = (const float4*)(Ain + (size_t)gr * 128 + k0);
                    va = ap[0]; vb = ap[1];
                } else {
                    const float4* ap = (const float4*)(g_agg + (size_t)gr * 128 + k0);
                    float4 a0 = ap[0], a1 = ap[1];
                    const float4* scp = (const float4*)(s_bn + k0);
                    const float4* shp = (const float4*)(s_bn + 128 + k0);
                    float4 s0 = scp[0], s1 = scp[1], h0 = shp[0], h1 = shp[1];
                    va.x = fmaxf(fmaf(a0.x, s0.x, h0.x), 0.f);
                    va.y = fmaxf(fmaf(a0.y, s0.y, h0.y), 0.f);
                    va.z = fmaxf(fmaf(a0.z, s0.z, h0.z), 0.f);
                    va.w = fmaxf(fmaf(a0.w, s0.w, h0.w), 0.f);
                    vb.x = fmaxf(fmaf(a1.x, s1.x, h1.x), 0.f);
                    vb.y = fmaxf(fmaf(a1.y, s1.y, h1.y), 0.f);
                    vb.z = fmaxf(fmaf(a1.z, s1.z, h1.z), 0.f);
                    vb.w = fmaxf(fmaf(a1.w, s1.w, h1.w), 0.f);
                    if (mode == 2) {
                        const float4* rp = (const float4*)(g_act + (size_t)gr * 128 + k0);
                        float4 r0 = rp[0], r1 = rp[1];
                        va.x += r0.x; va.y += r0.y; va.z += r0.z; va.w += r0.w;
                        vb.x += r1.x; vb.y += r1.y; vb.z += r1.z; vb.w += r1.w;
                    }
                    float4* op = (float4*)(g_act + (size_t)gr * 128 + k0);
                    op[0] = va; op[1] = vb;
                }
            }
            float vv[8] = {va.x, va.y, va.z, va.w, vb.x, vb.y, vb.z, vb.w};
            uint32_t hw[4], lw[4];
#pragma unroll
            for (int q = 0; q < 4; q++) {
                __nv_bfloat162 hb = __floats2bfloat162_rn(vv[2 * q], vv[2 * q + 1]);
                float ra = __bfloat162float(hb.x), rb = __bfloat162float(hb.y);
                __nv_bfloat162 lb = __floats2bfloat162_rn(vv[2 * q] - ra, vv[2 * q + 1] - rb);
                hw[q] = *(uint32_t*)&hb;
                lw[q] = *(uint32_t*)&lb;
            }
            size_t off = ((size_t)r * Pp + k0) * 2;
            *(uint4*)(sm + SM_AHI + off) = make_uint4(hw[0], hw[1], hw[2], hw[3]);
            *(uint4*)(sm + SM_ALO + off) = make_uint4(lw[0], lw[1], lw[2], lw[3]);
        }
    }
    __syncthreads();

    // main loop: warp tile 32 rows x 64 cols. mg = wid>>1 (8), ng = wid&1 (2)
    int mg = wid >> 1;
    int ng = wid & 1;
    int m0 = mg * 32;
    int nb = ng * 64;

    float acc[2][8][4];
#pragma unroll
    for (int t = 0; t < 2; t++)
#pragma unroll
        for (int nt = 0; nt < 8; nt++) {
            acc[t][nt][0] = 0.f; acc[t][nt][1] = 0.f;
            acc[t][nt][2] = 0.f; acc[t][nt][3] = 0.f;
        }

#pragma unroll 1
    for (int kc = 0; kc < 8; kc++) {
        int k0 = kc * 16;
        uint32_t ah[2][4], al[2][4];
#pragma unroll
        for (int t = 0; t < 2; t++) {
            size_t o0 = ((size_t)(m0 + t * 16 + gid) * Pp + k0 + tig * 2) * 2;
            size_t o1 = ((size_t)(m0 + t * 16 + 8 + gid) * Pp + k0 + tig * 2) * 2;
            ah[t][0] = *(const uint32_t*)(sm + SM_AHI + o0);
            ah[t][1] = *(const uint32_t*)(sm + SM_AHI + o1);
            ah[t][2] = *(const uint32_t*)(sm + SM_AHI + o0 + 16);
            ah[t][3] = *(const uint32_t*)(sm + SM_AHI + o1 + 16);
            al[t][0] = *(const uint32_t*)(sm + SM_ALO + o0);
            al[t][1] = *(const uint32_t*)(sm + SM_ALO + o1);
            al[t][2] = *(const uint32_t*)(sm + SM_ALO + o0 + 16);
            al[t][3] = *(const uint32_t*)(sm + SM_ALO + o1 + 16);
        }
#pragma unroll
        for (int nt = 0; nt < 8; nt++) {
            size_t bo = ((size_t)(nb + nt * 8 + gid) * Pp + k0 + tig * 2) * 2;
            uint32_t bh0 = *(const uint32_t*)(sm + SM_W + bo);
            uint32_t bh1 = *(const uint32_t*)(sm + SM_W + bo + 16);
            uint32_t bl0 = *(const uint32_t*)(sm + SM_W + WIMG_B + bo);
            uint32_t bl1 = *(const uint32_t*)(sm + SM_W + WIMG_B + bo + 16);
#pragma unroll
            for (int t = 0; t < 2; t++) {
                MMA_BF16(acc[t][nt], ah[t], bh0, bh1);
                MMA_BF16(acc[t][nt], ah[t], bl0, bl1);
                MMA_BF16(acc[t][nt], al[t], bh0, bh1);
            }
        }
    }

    // epilogue: scale by dinv, convert to fp16, store to g_h16
#pragma unroll
    for (int t = 0; t < 2; t++) {
        int r1 = row0 + m0 + t * 16 + gid;
        int r2 = r1 + 8;
        float dv1 = (r1 < M) ? g_dinv[r1] : 0.f;
        float dv2 = (r2 < M) ? g_dinv[r2] : 0.f;
#pragma unroll
        for (int nt = 0; nt < 8; nt++) {
            int c2 = ng * 32 + nt * 4 + tig;      // half2 index within row
            if (r1 < M) {
                __half2 p = __floats2half2_rn(acc[t][nt][0] * dv1, acc[t][nt][1] * dv1);
                ((uint32_t*)g_h16)[(size_t)r1 * 64 + c2] = *(uint32_t*)&p;
            }
            if (r2 < M) {
                __half2 p = __floats2half2_rn(acc[t][nt][2] * dv2, acc[t][nt][3] * dv2);
                ((uint32_t*)g_h16)[(size_t)r2 * 64 + c2] = *(uint32_t*)&p;
            }
        }
    }
}

// ------- gather (fp16 payload) + bias + fused BN partial stats -------
// agg[d] = dinv[d] * (h'[d] + sum_e h'[src_e]) + bias
__global__ __launch_bounds__(512) void k_gather(const float* __restrict__ bias, int bnidx) {
    __shared__ float ss[16 * 128];

    int tid = threadIdx.x;
    int wloc = tid >> 5;
    int lane = tid & 31;
    int wid = blockIdx.x * 16 + wloc;

    int beg = g_off[wid];
    int end = g_off[wid + 1];
    float dn = g_dinv[wid];

    const uint2* hv = (const uint2*)g_h16;
    uint2 hs = hv[(size_t)wid * 32 + lane];
    float2 f0 = __half22float2(*(__half2*)&hs.x);
    float2 f1 = __half22float2(*(__half2*)&hs.y);
    float4 acc = make_float4(f0.x, f0.y, f1.x, f1.y);
    float4 acc2 = make_float4(0.f, 0.f, 0.f, 0.f);

    const int* csr = g_csr;
    int e = beg;
    for (; e + 2 <= end; e += 2) {
        int s0 = csr[e];
        int s1 = csr[e + 1];
        uint2 v0 = hv[(size_t)s0 * 32 + lane];
        uint2 v1 = hv[(size_t)s1 * 32 + lane];
        float2 a0 = __half22float2(*(__half2*)&v0.x);
        float2 a1 = __half22float2(*(__half2*)&v0.y);
        float2 b0 = __half22float2(*(__half2*)&v1.x);
        float2 b1 = __half22float2(*(__half2*)&v1.y);
        acc.x += a0.x; acc.y += a0.y; acc.z += a1.x; acc.w += a1.y;
        acc2.x += b0.x; acc2.y += b0.y; acc2.z += b1.x; acc2.w += b1.y;
    }
    if (e < end) {
        int s0 = csr[e];
        uint2 v0 = hv[(size_t)s0 * 32 + lane];
        float2 a0 = __half22float2(*(__half2*)&v0.x);
        float2 a1 = __half22float2(*(__half2*)&v0.y);
        acc.x += a0.x; acc.y += a0.y; acc.z += a1.x; acc.w += a1.y;
    }
    acc.x += acc2.x; acc.y += acc2.y; acc.z += acc2.z; acc.w += acc2.w;

    float4 b4 = ((const float4*)bias)[lane];
    acc.x = fmaf(acc.x, dn, b4.x);
    acc.y = fmaf(acc.y, dn, b4.y);
    acc.z = fmaf(acc.z, dn, b4.z);
    acc.w = fmaf(acc.w, dn, b4.w);
    ((float4*)g_agg)[(size_t)wid * 32 + lane] = acc;

    int base = wloc * 128 + lane * 4;
    ss[base + 0] = acc.x; ss[base + 1] = acc.y; ss[base + 2] = acc.z; ss[base + 3] = acc.w;
    __syncthreads();

    if (tid < 256) {
        int c = tid & 127;
        int part = tid >> 7;
        float r = 0.f;
        if (part == 0) {
#pragma unroll
            for (int w = 0; w < 16; w++) r += ss[w * 128 + c];
        } else {
#pragma unroll
            for (int w = 0; w < 16; w++) { float v = ss[w * 128 + c]; r = fmaf(v, v, r); }
        }
        atomicAdd(&g_bnsum[bnidx][blockIdx.x & (BN_REP - 1)][part * 128 + c], r);
    }
}

// ---------------- pooling with fused layer-3 BN finalize+apply ----------------
#define PCHUNK 256
__global__ void k_pool(const int* __restrict__ batch,
                       const float* __restrict__ gam, const float* __restrict__ bet) {
    int c = threadIdx.x;
    float s = 0.f, q = 0.f;
#pragma unroll
    for (int r = 0; r < BN_REP; r++) {
        s += g_bnsum[2][r][c];
        q += g_bnsum[2][r][128 + c];
    }
    float mean = s * (1.0f / (float)Nn);
    float var = q * (1.0f / (float)Nn) - mean * mean;
    float sc = gam[c] * rsqrtf(var + EPSf);
    float sh = bet[c] - mean * sc;

    int start = blockIdx.x * PCHUNK;
    if (start >= Nn) return;
    int end = min(start + PCHUNK, Nn);
    float acc = 0.f, ccnt = 0.f;
    int gp = batch[start];
    for (int n = start; n < end; n++) {
        int g = batch[n];
        if (g != gp) {
            atomicAdd(&g_xsum[gp * 128 + c], acc);
            if (c == 0) atomicAdd(&g_cnt[gp], ccnt);
            acc = 0.f; ccnt = 0.f; gp = g;
        }
        float a = g_agg[(size_t)n * 128 + c];
        float v = fmaxf(fmaf(a, sc, sh), 0.f) + g_act[(size_t)n * 128 + c];
        acc += v;
        ccnt += 1.f;
    }
    atomicAdd(&g_xsum[gp * 128 + c], acc);
    if (c == 0) atomicAdd(&g_cnt[gp], ccnt);
}

// ---------------- MLP head ----------------
__global__ void k_mlp(const float* __restrict__ Wm1, const float* __restrict__ bm1,
                      const float* __restrict__ Wm2, const float* __restrict__ bm2,
                      float* __restrict__ out) {
    __shared__ float zs[128], zm[128], hid[128];
    int g = blockIdx.x, c = threadIdx.x;
    float cnt = fmaxf(g_cnt[g], 1.0f);
    float xs = g_xsum[g * 128 + c];
    zs[c] = xs;
    zm[c] = xs / cnt;
    __syncthreads();
    float acc = bm1[c];
#pragma unroll 8
    for (int k = 0; k < 128; k++)
        acc += zs[k] * Wm1[k * 128 + c] + zm[k] * Wm1[(128 + k) * 128 + c];
    hid[c] = fmaxf(acc, 0.f) * Wm2[c];
    __syncthreads();
    for (int s = 64; s > 0; s >>= 1) {
        if (c < s) hid[c] += hid[c + s];
        __syncthreads();
    }
    if (c == 0) out[g] = hid[0] + bm2[0];
}

// ---------------- host ----------------
extern "C" void kernel_launch(void* const* d_in, const int* in_sizes, int n_in,
                              void* d_out, int out_size) {
    const float *x, *W1, *b1, *W2, *b2, *W3, *b3;
    const float *g1, *be1, *g2, *be2, *g3, *be3;
    const float *Wm1, *bm1, *Wm2, *bm2;
    const int *ei, *batch;

    if (in_sizes[1] == 2 * Ee) {
        x   = (const float*)d_in[0];
        ei  = (const int*)  d_in[1];
        batch = (const int*)d_in[2];
        W1 = (const float*)d_in[3];  b1 = (const float*)d_in[4];
        W2 = (const float*)d_in[5];  b2 = (const float*)d_in[6];
        W3 = (const float*)d_in[7];  b3 = (const float*)d_in[8];
        g1 = (const float*)d_in[9];  be1 = (const float*)d_in[10];
        g2 = (const float*)d_in[11]; be2 = (const float*)d_in[12];
        g3 = (const float*)d_in[13]; be3 = (const float*)d_in[14];
        Wm1 = (const float*)d_in[15]; bm1 = (const float*)d_in[16];
        Wm2 = (const float*)d_in[17]; bm2 = (const float*)d_in[18];
    } else {
        x   = (const float*)d_in[0];
        W1 = (const float*)d_in[1];  b1 = (const float*)d_in[2];
        g1 = (const float*)d_in[3];  be1 = (const float*)d_in[4];
        W2 = (const float*)d_in[5];  b2 = (const float*)d_in[6];
        g2 = (const float*)d_in[7];  be2 = (const float*)d_in[8];
        W3 = (const float*)d_in[9];  b3 = (const float*)d_in[10];
        g3 = (const float*)d_in[11]; be3 = (const float*)d_in[12];
        Wm1 = (const float*)d_in[13]; bm1 = (const float*)d_in[14];
        Wm2 = (const float*)d_in[15]; bm2 = (const float*)d_in[16];
        ei  = (const int*)d_in[17];
        batch = (const int*)d_in[18];
    }

    const int* src = ei;
    const int* dst = ei + Ee;
    float* out = (float*)d_out;

    cudaFuncSetAttribute(gemm_tc, cudaFuncAttributeMaxDynamicSharedMemorySize, SM_TOTAL);

    const int ZB = (Nn + 255) / 256;          // 391
    const int EB = (Ee + 255) / 256;          // 6250
    const int GEMMB = (Nn + 255) / 256;       // 391 x 512
    const int GATB = (Nn + 15) / 16;          // 6250
    const int POOLB = (Nn + PCHUNK - 1) / PCHUNK;

    // launches 1-3
    k_zero_pre<<<ZB, 256>>>();
    k_deg<<<EB, 256>>>(dst);
    k_prep<<<DINVB + 384, 128>>>(W1, W2, W3);   // dinv + W split

    // launch 4: layer-1 GEMM (profiling slot); epilogue uses dinv
    gemm_tc<<<GEMMB, 512, SM_TOTAL>>>(x, 0, Nn, 0, 0, nullptr, nullptr);

    // CSR build
    k_scan1<<<NBLK, SCAN_BS>>>();
    k_scan2<<<1, 128>>>();
    k_scan3<<<ZB, 256>>>();
    k_fill<<<EB, 256>>>(src, dst);

    // layer 1 aggregate + BN stats
    k_gather<<<GATB, 512>>>(b1, 0);

    // layer 2
    gemm_tc<<<GEMMB, 512, SM_TOTAL>>>(nullptr, 1, Nn, 1, 0, g1, be1);
    k_gather<<<GATB, 512>>>(b2, 1);

    // layer 3
    gemm_tc<<<GEMMB, 512, SM_TOTAL>>>(nullptr, 2, Nn, 2, 1, g2, be2);
    k_gather<<<GATB, 512>>>(b3, 2);

    // pooling + MLP
    k_pool<<<POOLB, 128>>>(batch, g3, be3);
    k_mlp<<<Gg, 128>>>(Wm1, bm1, Wm2, bm2, out);
}